// round 8
// baseline (speedup 1.0000x reference)
#include <cuda_runtime.h>
#include <cstdint>

#define NNODES 40000
#define INDIM  128
#define HID    64
#define NEDGES 640000

typedef unsigned long long ull;

// ---------------- scratch (device globals) ----------------
__device__ float g_y[NNODES * HID];    // lin_l(x) per node
__device__ float g_r[NNODES * HID];    // lin_r(x) per node
__device__ float g_h[NNODES * HID];    // layer-1 activation
__device__ float g_inv[NNODES];        // 1/max(deg,1)
__device__ int   g_deg[NNODES];
__device__ int   g_off[NNODES + 1];
__device__ int   g_cursor[NNODES];
__device__ int   g_csr[NEDGES];        // src ids grouped by dst

// ---------------- zero degrees (int4) ----------------
__global__ void k_zero_deg() {
    int i = blockIdx.x * blockDim.x + threadIdx.x;
    if (i < NNODES / 4)
        ((int4*)g_deg)[i] = make_int4(0, 0, 0, 0);
}

// ---------------- degree count (int4 edge reads) ----------------
__global__ void k_count(const int* __restrict__ ei) {
    int i = blockIdx.x * blockDim.x + threadIdx.x;
    if (i >= NEDGES / 4) return;
    int4 d = ((const int4*)(ei + NEDGES))[i];
    atomicAdd(&g_deg[d.x], 1);
    atomicAdd(&g_deg[d.y], 1);
    atomicAdd(&g_deg[d.z], 1);
    atomicAdd(&g_deg[d.w], 1);
}

// ---------------- warp scan helper ----------------
__device__ __forceinline__ int warp_incl_scan(int v, int lane) {
#pragma unroll
    for (int o = 1; o < 32; o <<= 1) {
        int n = __shfl_up_sync(0xffffffffu, v, o);
        if (lane >= o) v += n;
    }
    return v;
}

// ---------------- single-block full scan: off/cursor/inv -------------
// 1024 threads x 40 contiguous values (threads >= 1000 idle).
#define SCAN_VPT 40
__global__ __launch_bounds__(1024) void k_scan_all() {
    __shared__ int warpsum[32];
    const int t = threadIdx.x;
    const int lane = t & 31, wid = t >> 5;
    const int base = t * SCAN_VPT;
    const bool act = (base < NNODES);

    int sum = 0;
    if (act) {
#pragma unroll 8
        for (int j = 0; j < SCAN_VPT; j++) sum += g_deg[base + j];
    }
    int incl = warp_incl_scan(sum, lane);
    if (lane == 31) warpsum[wid] = incl;
    __syncthreads();
    if (wid == 0) {
        int ws = warpsum[lane];
        ws = warp_incl_scan(ws, lane);
        warpsum[lane] = ws;
    }
    __syncthreads();
    int run = (wid ? warpsum[wid - 1] : 0) + incl - sum;  // exclusive prefix
    if (act) {
#pragma unroll 4
        for (int j = 0; j < SCAN_VPT; j++) {
            int d = g_deg[base + j];
            g_off[base + j] = run;
            g_cursor[base + j] = run;
            g_inv[base + j] = 1.0f / fmaxf((float)d, 1.0f);
            run += d;
        }
    }
    if (t == 0) g_off[NNODES] = NEDGES;
}

// ---------------- scatter edges into CSR (int4 edge reads) ------------
__global__ void k_scatter(const int* __restrict__ ei) {
    int i = blockIdx.x * blockDim.x + threadIdx.x;
    if (i >= NEDGES / 4) return;
    int4 s = ((const int4*)ei)[i];
    int4 d = ((const int4*)(ei + NEDGES))[i];
    g_csr[atomicAdd(&g_cursor[d.x], 1)] = s.x;
    g_csr[atomicAdd(&g_cursor[d.y], 1)] = s.y;
    g_csr[atomicAdd(&g_cursor[d.z], 1)] = s.z;
    g_csr[atomicAdd(&g_cursor[d.w], 1)] = s.w;
}

// ---------------- dual GEMM: [Y|R] = X @ [Wl|Wr]^T ----------------
// Block: 64 rows x 128 k, 256 threads. Thread: 4 k x 8 rows (4 f32x2 pairs).
template <int KI, bool FROMH>
__global__ __launch_bounds__(256, 4) void k_gemm_dual(
    const float* __restrict__ Xin, const float* __restrict__ Wl,
    const float* __restrict__ Wr) {
    __shared__ float Ws[32][132];  // [d][k]
    __shared__ float Xs[32][66];   // [d][row]

    const float* __restrict__ X = FROMH ? (const float*)g_h : Xin;

    const int t  = threadIdx.x;
    const int tc = t & 31;
    const int tw = t >> 5;
    const int k0 = tc << 2;
    const int r0 = tw << 3;
    const int rowBase = blockIdx.x << 6;

    ull acc[4][4];
#pragma unroll
    for (int a = 0; a < 4; a++)
#pragma unroll
        for (int b = 0; b < 4; b++) acc[a][b] = 0ULL;

    const int kw    = t >> 1;
    const int partW = t & 1;
    const float* __restrict__ Wg =
        (kw < HID) ? (Wl + (size_t)kw * KI) : (Wr + (size_t)(kw - HID) * KI);
    const int lrow  = t >> 2;
    const int partX = t & 3;
    const float* __restrict__ Xg =
        X + (size_t)(rowBase + lrow) * KI + partX * 8;

#pragma unroll 1
    for (int d0 = 0; d0 < KI; d0 += 32) {
#pragma unroll
        for (int j = 0; j < 4; j++) {
            float4 w = *(const float4*)(Wg + d0 + partW * 16 + j * 4);
            int dd = partW * 16 + j * 4;
            Ws[dd + 0][kw] = w.x; Ws[dd + 1][kw] = w.y;
            Ws[dd + 2][kw] = w.z; Ws[dd + 3][kw] = w.w;
        }
#pragma unroll
        for (int j = 0; j < 2; j++) {
            float4 v = *(const float4*)(Xg + d0 + j * 4);
            int dd = partX * 8 + j * 4;
            Xs[dd + 0][lrow] = v.x; Xs[dd + 1][lrow] = v.y;
            Xs[dd + 2][lrow] = v.z; Xs[dd + 3][lrow] = v.w;
        }
        __syncthreads();

#pragma unroll
        for (int d = 0; d < 32; d++) {
            float4 wv = *(const float4*)&Ws[d][k0];
            ull w2[4];
            unsigned int wu;
            wu = __float_as_uint(wv.x); asm("mov.b64 %0, {%1,%1};" : "=l"(w2[0]) : "r"(wu));
            wu = __float_as_uint(wv.y); asm("mov.b64 %0, {%1,%1};" : "=l"(w2[1]) : "r"(wu));
            wu = __float_as_uint(wv.z); asm("mov.b64 %0, {%1,%1};" : "=l"(w2[2]) : "r"(wu));
            wu = __float_as_uint(wv.w); asm("mov.b64 %0, {%1,%1};" : "=l"(w2[3]) : "r"(wu));
#pragma unroll
            for (int j = 0; j < 4; j++) {
                ull xp = *(const ull*)&Xs[d][r0 + 2 * j];
#pragma unroll
                for (int kk = 0; kk < 4; kk++)
                    asm("fma.rn.f32x2 %0, %1, %2, %0;"
                        : "+l"(acc[kk][j]) : "l"(w2[kk]), "l"(xp));
            }
        }
        __syncthreads();
    }

    float* __restrict__ Obase = (k0 < HID) ? (g_y + k0) : (g_r + (k0 - HID));
#pragma unroll
    for (int j = 0; j < 4; j++) {
        int row = rowBase + r0 + 2 * j;
        float2 f[4];
#pragma unroll
        for (int kk = 0; kk < 4; kk++) f[kk] = *(float2*)&acc[kk][j];
        float4 lo = make_float4(f[0].x, f[1].x, f[2].x, f[3].x);
        float4 hi = make_float4(f[0].y, f[1].y, f[2].y, f[3].y);
        *(float4*)(Obase + (size_t)row * HID) = lo;
        *(float4*)(Obase + (size_t)(row + 1) * HID) = hi;
    }
}

// ---------------- pull aggregation fused with epilogue ----------------
// One warp per dst node: out = mean(y[neighbors]) + bias + r  [+ relu]
template <bool RELU, bool TOH>
__global__ __launch_bounds__(256) void k_pull(
    const float* __restrict__ bias, float* __restrict__ outp) {
    int w = (blockIdx.x * blockDim.x + threadIdx.x) >> 5;
    int lane = threadIdx.x & 31;
    if (w >= NNODES) return;

    int beg = g_off[w], end = g_off[w + 1];
    float2 acc = make_float2(0.f, 0.f);

    for (int base = beg; base < end; base += 32) {
        int idx = base + lane;
        int my = (idx < end) ? g_csr[idx] : 0;
        int m = min(32, end - base);
#pragma unroll 4
        for (int j = 0; j < m; j++) {
            int s = __shfl_sync(0xffffffffu, my, j);
            float2 v = *(const float2*)(g_y + (size_t)s * HID + lane * 2);
            acc.x += v.x; acc.y += v.y;
        }
    }

    float inv = g_inv[w];
    float2 r = *(const float2*)(g_r + (size_t)w * HID + lane * 2);
    float2 b = *(const float2*)(bias + lane * 2);
    float2 o;
    o.x = fmaf(acc.x, inv, r.x + b.x);
    o.y = fmaf(acc.y, inv, r.y + b.y);
    if (RELU) { o.x = fmaxf(o.x, 0.f); o.y = fmaxf(o.y, 0.f); }
    float* dstp = TOH ? (g_h + (size_t)w * HID + lane * 2)
                      : (outp + (size_t)w * HID + lane * 2);
    *(float2*)dstp = o;
}

// ---------------- launch (single stream, fully serial) ----------------
extern "C" void kernel_launch(void* const* d_in, const int* in_sizes, int n_in,
                              void* d_out, int out_size) {
    const float* x   = (const float*)d_in[0];
    const int*   ei  = (const int*)d_in[1];
    const float* W1l = (const float*)d_in[2];
    const float* b1  = (const float*)d_in[3];
    const float* W1r = (const float*)d_in[4];
    const float* W2l = (const float*)d_in[5];
    const float* b2  = (const float*)d_in[6];
    const float* W2r = (const float*)d_in[7];
    float* out = (float*)d_out;

    const int gGemm = NNODES / 64;                 // 625
    const int gPull = (NNODES * 32 + 255) / 256;   // 5000
    const int gE4   = (NEDGES / 4 + 255) / 256;    // 625

    // CSR build
    k_zero_deg<<<(NNODES / 4 + 255) / 256, 256>>>();
    k_count<<<gE4, 256>>>(ei);
    k_scan_all<<<1, 1024>>>();
    k_scatter<<<gE4, 256>>>(ei);

    // layer 1
    k_gemm_dual<INDIM, false><<<gGemm, 256>>>(x, W1l, W1r);
    k_pull<true, true><<<gPull, 256>>>(b1, nullptr);

    // layer 2
    k_gemm_dual<HID, true><<<gGemm, 256>>>(nullptr, W2l, W2r);
    k_pull<false, false><<<gPull, 256>>>(b2, out);
}

// round 9
// speedup vs baseline: 2.5601x; 2.5601x over previous
#include <cuda_runtime.h>
#include <cstdint>

#define NNODES 40000
#define INDIM  128
#define HID    64
#define NEDGES 640000
#define NB_SCAN 157           // ceil(40000/256)

typedef unsigned long long ull;

// ---------------- scratch (device globals) ----------------
__device__ float g_y[NNODES * HID];    // lin_l(x) per node
__device__ float g_r[NNODES * HID];    // lin_r(x) per node
__device__ float g_h[NNODES * HID];    // layer-1 activation
__device__ float g_inv[NNODES];        // 1/max(deg,1)
__device__ int   g_deg[NNODES];
__device__ int   g_off[NNODES + 1];
__device__ int   g_cursor[NNODES];
__device__ int   g_csr[NEDGES];        // src ids grouped by dst
__device__ int   g_bsum[NB_SCAN];

// ---------------- zero degrees (int4) ----------------
__global__ void k_zero_deg() {
    int i = blockIdx.x * blockDim.x + threadIdx.x;
    if (i < NNODES / 4)
        ((int4*)g_deg)[i] = make_int4(0, 0, 0, 0);
}

// ---------------- degree count (int4 edge reads) ----------------
__global__ void k_count(const int* __restrict__ ei) {
    int i = blockIdx.x * blockDim.x + threadIdx.x;
    if (i >= NEDGES / 4) return;
    int4 d = ((const int4*)(ei + NEDGES))[i];
    atomicAdd(&g_deg[d.x], 1);
    atomicAdd(&g_deg[d.y], 1);
    atomicAdd(&g_deg[d.z], 1);
    atomicAdd(&g_deg[d.w], 1);
}

// ---------------- scan helpers ----------------
__device__ __forceinline__ int warp_incl_scan(int v, int lane) {
#pragma unroll
    for (int o = 1; o < 32; o <<= 1) {
        int n = __shfl_up_sync(0xffffffffu, v, o);
        if (lane >= o) v += n;
    }
    return v;
}

__device__ __forceinline__ int block_excl_scan256(int v, int tid, int* total) {
    __shared__ int warpsum[8];
    int lane = tid & 31, wid = tid >> 5;
    int incl = warp_incl_scan(v, lane);
    if (lane == 31) warpsum[wid] = incl;
    __syncthreads();
    if (wid == 0) {
        int ws = (lane < 8) ? warpsum[lane] : 0;
        ws = warp_incl_scan(ws, lane);
        if (lane < 8) warpsum[lane] = ws;
    }
    __syncthreads();
    int base = wid ? warpsum[wid - 1] : 0;
    if (total) *total = warpsum[7];
    return base + incl - v;
}

// ---------------- scan phase A: local prefix + block sums -------------
// Stores within-block exclusive prefix in g_off[i] (temp), block total in g_bsum.
__global__ void k_scanA() {
    int i = blockIdx.x * 256 + threadIdx.x;
    int v = (i < NNODES) ? g_deg[i] : 0;
    int tot;
    int ex = block_excl_scan256(v, threadIdx.x, &tot);
    if (i < NNODES) g_off[i] = ex;
    if (threadIdx.x == 0) g_bsum[blockIdx.x] = tot;
}

// ---------------- scan phase C: add block base, finalize ---------------
// Each block reduces g_bsum[0..blockIdx) with its own threads (<=157 values).
__global__ void k_scanC() {
    __shared__ int warpsum[8];
    __shared__ int sbase;
    const int t = threadIdx.x;
    const int lane = t & 31, wid = t >> 5;

    int v = (t < (int)blockIdx.x) ? g_bsum[t] : 0;   // NB_SCAN <= 256
#pragma unroll
    for (int o = 16; o > 0; o >>= 1) v += __shfl_down_sync(0xffffffffu, v, o);
    if (lane == 0) warpsum[wid] = v;
    __syncthreads();
    if (t == 0) {
        int s = 0;
#pragma unroll
        for (int j = 0; j < 8; j++) s += warpsum[j];
        sbase = s;
    }
    __syncthreads();

    int i = blockIdx.x * 256 + t;
    if (i < NNODES) {
        int off = sbase + g_off[i];
        int d = g_deg[i];
        g_off[i] = off;
        g_cursor[i] = off;
        g_inv[i] = 1.0f / fmaxf((float)d, 1.0f);
    }
    if (i == 0) g_off[NNODES] = NEDGES;
}

// ---------------- scatter edges into CSR (int4 edge reads) ------------
__global__ void k_scatter(const int* __restrict__ ei) {
    int i = blockIdx.x * blockDim.x + threadIdx.x;
    if (i >= NEDGES / 4) return;
    int4 s = ((const int4*)ei)[i];
    int4 d = ((const int4*)(ei + NEDGES))[i];
    g_csr[atomicAdd(&g_cursor[d.x], 1)] = s.x;
    g_csr[atomicAdd(&g_cursor[d.y], 1)] = s.y;
    g_csr[atomicAdd(&g_cursor[d.z], 1)] = s.z;
    g_csr[atomicAdd(&g_cursor[d.w], 1)] = s.w;
}

// ---------------- dual GEMM: [Y|R] = X @ [Wl|Wr]^T ----------------
// Block: 64 rows x 128 k, 256 threads. Thread: 4 k x 8 rows (4 f32x2 pairs).
template <int KI, bool FROMH>
__global__ __launch_bounds__(256, 4) void k_gemm_dual(
    const float* __restrict__ Xin, const float* __restrict__ Wl,
    const float* __restrict__ Wr) {
    __shared__ float Ws[32][132];  // [d][k]
    __shared__ float Xs[32][66];   // [d][row]

    const float* __restrict__ X = FROMH ? (const float*)g_h : Xin;

    const int t  = threadIdx.x;
    const int tc = t & 31;
    const int tw = t >> 5;
    const int k0 = tc << 2;
    const int r0 = tw << 3;
    const int rowBase = blockIdx.x << 6;

    ull acc[4][4];
#pragma unroll
    for (int a = 0; a < 4; a++)
#pragma unroll
        for (int b = 0; b < 4; b++) acc[a][b] = 0ULL;

    const int kw    = t >> 1;
    const int partW = t & 1;
    const float* __restrict__ Wg =
        (kw < HID) ? (Wl + (size_t)kw * KI) : (Wr + (size_t)(kw - HID) * KI);
    const int lrow  = t >> 2;
    const int partX = t & 3;
    const float* __restrict__ Xg =
        X + (size_t)(rowBase + lrow) * KI + partX * 8;

#pragma unroll 1
    for (int d0 = 0; d0 < KI; d0 += 32) {
#pragma unroll
        for (int j = 0; j < 4; j++) {
            float4 w = *(const float4*)(Wg + d0 + partW * 16 + j * 4);
            int dd = partW * 16 + j * 4;
            Ws[dd + 0][kw] = w.x; Ws[dd + 1][kw] = w.y;
            Ws[dd + 2][kw] = w.z; Ws[dd + 3][kw] = w.w;
        }
#pragma unroll
        for (int j = 0; j < 2; j++) {
            float4 v = *(const float4*)(Xg + d0 + j * 4);
            int dd = partX * 8 + j * 4;
            Xs[dd + 0][lrow] = v.x; Xs[dd + 1][lrow] = v.y;
            Xs[dd + 2][lrow] = v.z; Xs[dd + 3][lrow] = v.w;
        }
        __syncthreads();

#pragma unroll
        for (int d = 0; d < 32; d++) {
            float4 wv = *(const float4*)&Ws[d][k0];
            ull w2[4];
            unsigned int wu;
            wu = __float_as_uint(wv.x); asm("mov.b64 %0, {%1,%1};" : "=l"(w2[0]) : "r"(wu));
            wu = __float_as_uint(wv.y); asm("mov.b64 %0, {%1,%1};" : "=l"(w2[1]) : "r"(wu));
            wu = __float_as_uint(wv.z); asm("mov.b64 %0, {%1,%1};" : "=l"(w2[2]) : "r"(wu));
            wu = __float_as_uint(wv.w); asm("mov.b64 %0, {%1,%1};" : "=l"(w2[3]) : "r"(wu));
#pragma unroll
            for (int j = 0; j < 4; j++) {
                ull xp = *(const ull*)&Xs[d][r0 + 2 * j];
#pragma unroll
                for (int kk = 0; kk < 4; kk++)
                    asm("fma.rn.f32x2 %0, %1, %2, %0;"
                        : "+l"(acc[kk][j]) : "l"(w2[kk]), "l"(xp));
            }
        }
        __syncthreads();
    }

    float* __restrict__ Obase = (k0 < HID) ? (g_y + k0) : (g_r + (k0 - HID));
#pragma unroll
    for (int j = 0; j < 4; j++) {
        int row = rowBase + r0 + 2 * j;
        float2 f[4];
#pragma unroll
        for (int kk = 0; kk < 4; kk++) f[kk] = *(float2*)&acc[kk][j];
        float4 lo = make_float4(f[0].x, f[1].x, f[2].x, f[3].x);
        float4 hi = make_float4(f[0].y, f[1].y, f[2].y, f[3].y);
        *(float4*)(Obase + (size_t)row * HID) = lo;
        *(float4*)(Obase + (size_t)(row + 1) * HID) = hi;
    }
}

// ---------------- pull aggregation fused with epilogue ----------------
// One warp per dst node: out = mean(y[neighbors]) + bias + r  [+ relu]
template <bool RELU, bool TOH>
__global__ __launch_bounds__(256) void k_pull(
    const float* __restrict__ bias, float* __restrict__ outp) {
    int w = (blockIdx.x * blockDim.x + threadIdx.x) >> 5;
    int lane = threadIdx.x & 31;
    if (w >= NNODES) return;

    int beg = g_off[w], end = g_off[w + 1];
    float2 acc = make_float2(0.f, 0.f);

    for (int base = beg; base < end; base += 32) {
        int idx = base + lane;
        int my = (idx < end) ? g_csr[idx] : 0;
        int m = min(32, end - base);
#pragma unroll 4
        for (int j = 0; j < m; j++) {
            int s = __shfl_sync(0xffffffffu, my, j);
            float2 v = *(const float2*)(g_y + (size_t)s * HID + lane * 2);
            acc.x += v.x; acc.y += v.y;
        }
    }

    float inv = g_inv[w];
    float2 r = *(const float2*)(g_r + (size_t)w * HID + lane * 2);
    float2 b = *(const float2*)(bias + lane * 2);
    float2 o;
    o.x = fmaf(acc.x, inv, r.x + b.x);
    o.y = fmaf(acc.y, inv, r.y + b.y);
    if (RELU) { o.x = fmaxf(o.x, 0.f); o.y = fmaxf(o.y, 0.f); }
    float* dstp = TOH ? (g_h + (size_t)w * HID + lane * 2)
                      : (outp + (size_t)w * HID + lane * 2);
    *(float2*)dstp = o;
}

// ---------------- launch (single stream, fully serial) ----------------
extern "C" void kernel_launch(void* const* d_in, const int* in_sizes, int n_in,
                              void* d_out, int out_size) {
    const float* x   = (const float*)d_in[0];
    const int*   ei  = (const int*)d_in[1];
    const float* W1l = (const float*)d_in[2];
    const float* b1  = (const float*)d_in[3];
    const float* W1r = (const float*)d_in[4];
    const float* W2l = (const float*)d_in[5];
    const float* b2  = (const float*)d_in[6];
    const float* W2r = (const float*)d_in[7];
    float* out = (float*)d_out;

    const int gGemm = NNODES / 64;                 // 625
    const int gPull = (NNODES * 32 + 255) / 256;   // 5000
    const int gE4   = (NEDGES / 4 + 255) / 256;    // 625

    // CSR build (parallel scan: 2 launches)
    k_zero_deg<<<(NNODES / 4 + 255) / 256, 256>>>();
    k_count<<<gE4, 256>>>(ei);
    k_scanA<<<NB_SCAN, 256>>>();
    k_scanC<<<NB_SCAN, 256>>>();
    k_scatter<<<gE4, 256>>>(ei);

    // layer 1
    k_gemm_dual<INDIM, false><<<gGemm, 256>>>(x, W1l, W1r);
    k_pull<true, true><<<gPull, 256>>>(b1, nullptr);

    // layer 2
    k_gemm_dual<HID, true><<<gGemm, 256>>>(nullptr, W2l, W2r);
    k_pull<false, false><<<gPull, 256>>>(b2, out);
}

// round 10
// speedup vs baseline: 2.8715x; 1.1216x over previous
#include <cuda_runtime.h>
#include <cstdint>

#define NNODES 40000
#define INDIM  128
#define HID    64
#define NEDGES 640000
#define NB_SCAN 157           // ceil(40000/256)

typedef unsigned long long ull;

// ---------------- scratch (device globals) ----------------
__device__ float g_y[NNODES * HID];    // lin_l(x) per node
__device__ float g_r[NNODES * HID];    // lin_r(x) per node
__device__ float g_h[NNODES * HID];    // layer-1 activation
__device__ float g_inv[NNODES];        // 1/max(deg,1)
__device__ int   g_deg[NNODES];        // zero-init; re-zeroed by k_scanC each call
__device__ int   g_off[NNODES + 1];
__device__ int   g_cursor[NNODES];
__device__ int   g_csr[NEDGES];        // src ids grouped by dst
__device__ int   g_bsum[NB_SCAN];

// ---------------- degree count (int4 edge reads) ----------------
__global__ void k_count(const int* __restrict__ ei) {
    int i = blockIdx.x * blockDim.x + threadIdx.x;
    if (i >= NEDGES / 4) return;
    int4 d = ((const int4*)(ei + NEDGES))[i];
    atomicAdd(&g_deg[d.x], 1);
    atomicAdd(&g_deg[d.y], 1);
    atomicAdd(&g_deg[d.z], 1);
    atomicAdd(&g_deg[d.w], 1);
}

// ---------------- scan helpers ----------------
__device__ __forceinline__ int warp_incl_scan(int v, int lane) {
#pragma unroll
    for (int o = 1; o < 32; o <<= 1) {
        int n = __shfl_up_sync(0xffffffffu, v, o);
        if (lane >= o) v += n;
    }
    return v;
}

__device__ __forceinline__ int block_excl_scan256(int v, int tid, int* total) {
    __shared__ int warpsum[8];
    int lane = tid & 31, wid = tid >> 5;
    int incl = warp_incl_scan(v, lane);
    if (lane == 31) warpsum[wid] = incl;
    __syncthreads();
    if (wid == 0) {
        int ws = (lane < 8) ? warpsum[lane] : 0;
        ws = warp_incl_scan(ws, lane);
        if (lane < 8) warpsum[lane] = ws;
    }
    __syncthreads();
    int base = wid ? warpsum[wid - 1] : 0;
    if (total) *total = warpsum[7];
    return base + incl - v;
}

// ---------------- scan phase A: local prefix + block sums -------------
__global__ void k_scanA() {
    int i = blockIdx.x * 256 + threadIdx.x;
    int v = (i < NNODES) ? g_deg[i] : 0;
    int tot;
    int ex = block_excl_scan256(v, threadIdx.x, &tot);
    if (i < NNODES) g_off[i] = ex;
    if (threadIdx.x == 0) g_bsum[blockIdx.x] = tot;
}

// ---------------- scan phase C: add block base, finalize, re-zero deg --
__global__ void k_scanC() {
    __shared__ int warpsum[8];
    __shared__ int sbase;
    const int t = threadIdx.x;
    const int lane = t & 31, wid = t >> 5;

    int v = (t < (int)blockIdx.x) ? g_bsum[t] : 0;   // NB_SCAN <= 256
#pragma unroll
    for (int o = 16; o > 0; o >>= 1) v += __shfl_down_sync(0xffffffffu, v, o);
    if (lane == 0) warpsum[wid] = v;
    __syncthreads();
    if (t == 0) {
        int s = 0;
#pragma unroll
        for (int j = 0; j < 8; j++) s += warpsum[j];
        sbase = s;
    }
    __syncthreads();

    int i = blockIdx.x * 256 + t;
    if (i < NNODES) {
        int off = sbase + g_off[i];
        int d = g_deg[i];
        g_off[i] = off;
        g_cursor[i] = off;
        g_inv[i] = 1.0f / fmaxf((float)d, 1.0f);
        g_deg[i] = 0;                    // restore invariant for next call
    }
    if (i == 0) g_off[NNODES] = NEDGES;
}

// ---------------- scatter edges into CSR (int4 edge reads) ------------
__global__ void k_scatter(const int* __restrict__ ei) {
    int i = blockIdx.x * blockDim.x + threadIdx.x;
    if (i >= NEDGES / 4) return;
    int4 s = ((const int4*)ei)[i];
    int4 d = ((const int4*)(ei + NEDGES))[i];
    g_csr[atomicAdd(&g_cursor[d.x], 1)] = s.x;
    g_csr[atomicAdd(&g_cursor[d.y], 1)] = s.y;
    g_csr[atomicAdd(&g_cursor[d.z], 1)] = s.z;
    g_csr[atomicAdd(&g_cursor[d.w], 1)] = s.w;
}

// ---------------- dual GEMM: [Y|R] = X @ [Wl|Wr]^T ----------------
template <int KI, bool FROMH>
__global__ __launch_bounds__(256, 4) void k_gemm_dual(
    const float* __restrict__ Xin, const float* __restrict__ Wl,
    const float* __restrict__ Wr) {
    __shared__ float Ws[32][132];  // [d][k]
    __shared__ float Xs[32][66];   // [d][row]

    const float* __restrict__ X = FROMH ? (const float*)g_h : Xin;

    const int t  = threadIdx.x;
    const int tc = t & 31;
    const int tw = t >> 5;
    const int k0 = tc << 2;
    const int r0 = tw << 3;
    const int rowBase = blockIdx.x << 6;

    ull acc[4][4];
#pragma unroll
    for (int a = 0; a < 4; a++)
#pragma unroll
        for (int b = 0; b < 4; b++) acc[a][b] = 0ULL;

    const int kw    = t >> 1;
    const int partW = t & 1;
    const float* __restrict__ Wg =
        (kw < HID) ? (Wl + (size_t)kw * KI) : (Wr + (size_t)(kw - HID) * KI);
    const int lrow  = t >> 2;
    const int partX = t & 3;
    const float* __restrict__ Xg =
        X + (size_t)(rowBase + lrow) * KI + partX * 8;

#pragma unroll 1
    for (int d0 = 0; d0 < KI; d0 += 32) {
#pragma unroll
        for (int j = 0; j < 4; j++) {
            float4 w = *(const float4*)(Wg + d0 + partW * 16 + j * 4);
            int dd = partW * 16 + j * 4;
            Ws[dd + 0][kw] = w.x; Ws[dd + 1][kw] = w.y;
            Ws[dd + 2][kw] = w.z; Ws[dd + 3][kw] = w.w;
        }
#pragma unroll
        for (int j = 0; j < 2; j++) {
            float4 v = *(const float4*)(Xg + d0 + j * 4);
            int dd = partX * 8 + j * 4;
            Xs[dd + 0][lrow] = v.x; Xs[dd + 1][lrow] = v.y;
            Xs[dd + 2][lrow] = v.z; Xs[dd + 3][lrow] = v.w;
        }
        __syncthreads();

#pragma unroll
        for (int d = 0; d < 32; d++) {
            float4 wv = *(const float4*)&Ws[d][k0];
            ull w2[4];
            unsigned int wu;
            wu = __float_as_uint(wv.x); asm("mov.b64 %0, {%1,%1};" : "=l"(w2[0]) : "r"(wu));
            wu = __float_as_uint(wv.y); asm("mov.b64 %0, {%1,%1};" : "=l"(w2[1]) : "r"(wu));
            wu = __float_as_uint(wv.z); asm("mov.b64 %0, {%1,%1};" : "=l"(w2[2]) : "r"(wu));
            wu = __float_as_uint(wv.w); asm("mov.b64 %0, {%1,%1};" : "=l"(w2[3]) : "r"(wu));
#pragma unroll
            for (int j = 0; j < 4; j++) {
                ull xp = *(const ull*)&Xs[d][r0 + 2 * j];
#pragma unroll
                for (int kk = 0; kk < 4; kk++)
                    asm("fma.rn.f32x2 %0, %1, %2, %0;"
                        : "+l"(acc[kk][j]) : "l"(w2[kk]), "l"(xp));
            }
        }
        __syncthreads();
    }

    float* __restrict__ Obase = (k0 < HID) ? (g_y + k0) : (g_r + (k0 - HID));
#pragma unroll
    for (int j = 0; j < 4; j++) {
        int row = rowBase + r0 + 2 * j;
        float2 f[4];
#pragma unroll
        for (int kk = 0; kk < 4; kk++) f[kk] = *(float2*)&acc[kk][j];
        float4 lo = make_float4(f[0].x, f[1].x, f[2].x, f[3].x);
        float4 hi = make_float4(f[0].y, f[1].y, f[2].y, f[3].y);
        *(float4*)(Obase + (size_t)row * HID) = lo;
        *(float4*)(Obase + (size_t)(row + 1) * HID) = hi;
    }
}

// ---------------- pull aggregation fused with epilogue ----------------
template <bool RELU, bool TOH>
__global__ __launch_bounds__(256) void k_pull(
    const float* __restrict__ bias, float* __restrict__ outp) {
    int w = (blockIdx.x * blockDim.x + threadIdx.x) >> 5;
    int lane = threadIdx.x & 31;
    if (w >= NNODES) return;

    int beg = g_off[w], end = g_off[w + 1];
    float2 acc = make_float2(0.f, 0.f);

    for (int base = beg; base < end; base += 32) {
        int idx = base + lane;
        int my = (idx < end) ? g_csr[idx] : 0;
        int m = min(32, end - base);
#pragma unroll 4
        for (int j = 0; j < m; j++) {
            int s = __shfl_sync(0xffffffffu, my, j);
            float2 v = *(const float2*)(g_y + (size_t)s * HID + lane * 2);
            acc.x += v.x; acc.y += v.y;
        }
    }

    float inv = g_inv[w];
    float2 r = *(const float2*)(g_r + (size_t)w * HID + lane * 2);
    float2 b = *(const float2*)(bias + lane * 2);
    float2 o;
    o.x = fmaf(acc.x, inv, r.x + b.x);
    o.y = fmaf(acc.y, inv, r.y + b.y);
    if (RELU) { o.x = fmaxf(o.x, 0.f); o.y = fmaxf(o.y, 0.f); }
    float* dstp = TOH ? (g_h + (size_t)w * HID + lane * 2)
                      : (outp + (size_t)w * HID + lane * 2);
    *(float2*)dstp = o;
}

// ---------------- launch: CSR on side stream ∥ GEMM1 on main ----------
extern "C" void kernel_launch(void* const* d_in, const int* in_sizes, int n_in,
                              void* d_out, int out_size) {
    const float* x   = (const float*)d_in[0];
    const int*   ei  = (const int*)d_in[1];
    const float* W1l = (const float*)d_in[2];
    const float* b1  = (const float*)d_in[3];
    const float* W1r = (const float*)d_in[4];
    const float* W2l = (const float*)d_in[5];
    const float* b2  = (const float*)d_in[6];
    const float* W2r = (const float*)d_in[7];
    float* out = (float*)d_out;

    const int gGemm = NNODES / 64;                 // 625
    const int gPull = (NNODES * 32 + 255) / 256;   // 5000
    const int gE4   = (NEDGES / 4 + 255) / 256;    // 625

    static cudaStream_t s2 = nullptr;
    static cudaEvent_t  eFork = nullptr, eJoin = nullptr;
    static bool forked = false;
    if (!s2) {
        if (cudaStreamCreateWithFlags(&s2, cudaStreamNonBlocking) == cudaSuccess &&
            cudaEventCreateWithFlags(&eFork, cudaEventDisableTiming) == cudaSuccess &&
            cudaEventCreateWithFlags(&eJoin, cudaEventDisableTiming) == cudaSuccess)
            forked = true;
    }

    if (forked) {
        cudaEventRecord(eFork, 0);
        cudaStreamWaitEvent(s2, eFork, 0);
        k_count<<<gE4, 256, 0, s2>>>(ei);
        k_scanA<<<NB_SCAN, 256, 0, s2>>>();
        k_scanC<<<NB_SCAN, 256, 0, s2>>>();
        k_scatter<<<gE4, 256, 0, s2>>>(ei);
        cudaEventRecord(eJoin, s2);

        k_gemm_dual<INDIM, false><<<gGemm, 256>>>(x, W1l, W1r);

        cudaStreamWaitEvent(0, eJoin, 0);
    } else {
        k_count<<<gE4, 256>>>(ei);
        k_scanA<<<NB_SCAN, 256>>>();
        k_scanC<<<NB_SCAN, 256>>>();
        k_scatter<<<gE4, 256>>>(ei);
        k_gemm_dual<INDIM, false><<<gGemm, 256>>>(x, W1l, W1r);
    }

    // layer 1 aggregate + epilogue
    k_pull<true, true><<<gPull, 256>>>(b1, nullptr);

    // layer 2
    k_gemm_dual<HID, true><<<gGemm, 256>>>(nullptr, W2l, W2r);
    k_pull<false, false><<<gPull, 256>>>(b2, out);
}